// round 8
// baseline (speedup 1.0000x reference)
#include <cuda_runtime.h>
#include <cuda_fp16.h>
#include <cstdint>

#define HIDDEN   1024
#define NLAYERS  20
#define M_TOTAL  8192

// ---- GEMM tiling (fp16 HMMA m16n8k16) ----
#define BM 128
#define BN 128
#define BKH 64                    // K per tile, in halves -> 128B smem rows
#define KT (HIDDEN/BKH)           // 16
#define ROWB 128
#define A_STAGE (BM*ROWB)         // 16384 B
#define B_STAGE (BN*ROWB)         // 16384 B
#define STAGE   (A_STAGE+B_STAGE) // 32768 B
#define STAGES  3
#define SMEM_BYTES (STAGES*STAGE) // 98304 B -> 2 CTAs/SM

__device__ __half g_wsum[HIDDEN*HIDDEN];     // 2 MB  (pre-summed weights, fp16)
__device__ __half g_ax[M_TOTAL*HIDDEN];      // 16 MB (activations, fp16)
__device__ int    g_cnt[M_TOTAL/BM];         // 64 row-block completion counters

// ---------------------------------------------------------------------------
__device__ __forceinline__ uint32_t smem_u32(const void* p) {
    uint32_t a;
    asm("{ .reg .u64 t; cvta.to.shared.u64 t, %1; cvt.u32.u64 %0, t; }" : "=r"(a) : "l"(p));
    return a;
}
__device__ __forceinline__ void cp16(uint32_t saddr, const void* g) {
    asm volatile("cp.async.cg.shared.global [%0], [%1], 16;" :: "r"(saddr), "l"(g));
}
__device__ __forceinline__ uint32_t f2_to_h2(float lo, float hi) {
    uint32_t r;
    asm("cvt.rn.f16x2.f32 %0, %1, %2;" : "=r"(r) : "f"(hi), "f"(lo));
    return r;
}

// ---------------------------------------------------------------------------
// Kernel 0 (fused prep):
//   blocks [0, 8192):    g_ax  = fp16(x)                 (8M elems)
//   blocks [8192, 9216): g_wsum = fp16(mean_l conv_w[l]) (1M elems)
//   block 0 additionally zeroes g_cnt (graph-replay-safe)
// ---------------------------------------------------------------------------
__global__ void __launch_bounds__(256)
prep_kernel(const float* __restrict__ x, const float* __restrict__ cw) {
    const int b = blockIdx.x, t = threadIdx.x;
    if (b == 0 && t < M_TOTAL/BM) g_cnt[t] = 0;
    if (b < M_TOTAL * HIDDEN / 1024) {
        const int i4 = b * 256 + t;                    // float4 index
        float4 v = ((const float4*)x)[i4];
        uint2 h;
        h.x = f2_to_h2(v.x, v.y);
        h.y = f2_to_h2(v.z, v.w);
        ((uint2*)g_ax)[i4] = h;
    } else {
        const int i4 = (b - M_TOTAL * HIDDEN / 1024) * 256 + t;   // 0..262143
        const float4* cw4 = (const float4*)cw;
        float4 a0 = cw4[i4];
        float4 a1 = cw4[(HIDDEN*HIDDEN/4) + i4];
#pragma unroll
        for (int l = 2; l < NLAYERS; l += 2) {
            float4 v0 = cw4[l       * (HIDDEN*HIDDEN/4) + i4];
            float4 v1 = cw4[(l + 1) * (HIDDEN*HIDDEN/4) + i4];
            a0.x += v0.x; a0.y += v0.y; a0.z += v0.z; a0.w += v0.w;
            a1.x += v1.x; a1.y += v1.y; a1.z += v1.z; a1.w += v1.w;
        }
        const float s = 1.0f / (float)NLAYERS;
        uint2 h;
        h.x = f2_to_h2((a0.x + a1.x) * s, (a0.y + a1.y) * s);
        h.y = f2_to_h2((a0.z + a1.z) * s, (a0.w + a1.w) * s);
        ((uint2*)g_wsum)[i4] = h;
    }
}

// ---------------------------------------------------------------------------
// Kernel 1: fp16 GEMM + fused row-block RMS-norm tail
//   out[m][n] = sum_k Ax[m][k] * Wsum[n][k]; last CTA per row-block normalizes.
// ---------------------------------------------------------------------------
__global__ void __launch_bounds__(256, 2)
gemm_kernel(float* __restrict__ out, const float* __restrict__ nw) {
    extern __shared__ char smem[];
    const uint32_t sbase = smem_u32(smem);

    const int tid  = threadIdx.x;
    const int lane = tid & 31;
    const int warp = tid >> 5;
    const int wm   = (warp & 1) * 64;
    const int wn   = (warp >> 1) * 32;
    const int mBase = blockIdx.y * BM;
    const int nBase = blockIdx.x * BN;

    float acc[4][4][4];
#pragma unroll
    for (int mi = 0; mi < 4; ++mi)
#pragma unroll
        for (int ni = 0; ni < 4; ++ni)
#pragma unroll
            for (int c = 0; c < 4; ++c) acc[mi][ni][c] = 0.0f;

    auto load_stage = [&](int s, int k0h) {
        const uint32_t sa = sbase + (uint32_t)s * STAGE;
        const uint32_t sb = sa + A_STAGE;
#pragma unroll
        for (int i = 0; i < 4; ++i) {
            const int c = i * 256 + tid;          // 0..1023
            const int row = c >> 3, ch = c & 7;
            const uint32_t off = (uint32_t)c * 16u;
            cp16(sa + (off ^ ((off >> 3) & 0x70u)),
                 g_ax + (size_t)(mBase + row) * HIDDEN + k0h + ch * 8);
        }
#pragma unroll
        for (int i = 0; i < 4; ++i) {
            const int c = i * 256 + tid;
            const int row = c >> 3, ch = c & 7;
            const uint32_t off = (uint32_t)c * 16u;
            cp16(sb + (off ^ ((off >> 3) & 0x70u)),
                 g_wsum + (size_t)(nBase + row) * HIDDEN + k0h + ch * 8);
        }
        asm volatile("cp.async.commit_group;");
    };

    load_stage(0, 0);
    load_stage(1, BKH);

    for (int kt = 0; kt < KT; ++kt) {
        asm volatile("cp.async.wait_group 1;");
        __syncthreads();
        if (kt + 2 < KT) load_stage((kt + 2) % STAGES, (kt + 2) * BKH);
        else             asm volatile("cp.async.commit_group;");

        const uint32_t sa = sbase + (uint32_t)(kt % STAGES) * STAGE;
        const uint32_t sb = sa + A_STAGE;

#pragma unroll
        for (int kk = 0; kk < 4; ++kk) {
            const uint32_t colb = (uint32_t)(kk * 32 + (lane >> 4) * 16);
            uint32_t af[4][4], bf[2][4];
#pragma unroll
            for (int mi = 0; mi < 4; ++mi) {
                const uint32_t off = (uint32_t)(wm + mi * 16 + (lane & 15)) * ROWB + colb;
                const uint32_t addr = sa + (off ^ ((off >> 3) & 0x70u));
                asm volatile("ldmatrix.sync.aligned.m8n8.x4.shared.b16 {%0,%1,%2,%3}, [%4];"
                             : "=r"(af[mi][0]), "=r"(af[mi][1]), "=r"(af[mi][2]), "=r"(af[mi][3])
                             : "r"(addr));
            }
#pragma unroll
            for (int np = 0; np < 2; ++np) {
                const uint32_t off = (uint32_t)(wn + np * 16 + (lane & 15)) * ROWB + colb;
                const uint32_t addr = sb + (off ^ ((off >> 3) & 0x70u));
                asm volatile("ldmatrix.sync.aligned.m8n8.x4.shared.b16 {%0,%1,%2,%3}, [%4];"
                             : "=r"(bf[np][0]), "=r"(bf[np][1]), "=r"(bf[np][2]), "=r"(bf[np][3])
                             : "r"(addr));
            }
#pragma unroll
            for (int mi = 0; mi < 4; ++mi) {
#pragma unroll
                for (int np = 0; np < 2; ++np) {
                    asm volatile(
                        "mma.sync.aligned.m16n8k16.row.col.f32.f16.f16.f32 "
                        "{%0,%1,%2,%3}, {%4,%5,%6,%7}, {%8,%9}, {%0,%1,%2,%3};"
                        : "+f"(acc[mi][np*2][0]), "+f"(acc[mi][np*2][1]),
                          "+f"(acc[mi][np*2][2]), "+f"(acc[mi][np*2][3])
                        : "r"(af[mi][0]), "r"(af[mi][1]), "r"(af[mi][2]), "r"(af[mi][3]),
                          "r"(bf[np][0]), "r"(bf[np][2]));
                    asm volatile(
                        "mma.sync.aligned.m16n8k16.row.col.f32.f16.f16.f32 "
                        "{%0,%1,%2,%3}, {%4,%5,%6,%7}, {%8,%9}, {%0,%1,%2,%3};"
                        : "+f"(acc[mi][np*2+1][0]), "+f"(acc[mi][np*2+1][1]),
                          "+f"(acc[mi][np*2+1][2]), "+f"(acc[mi][np*2+1][3])
                        : "r"(af[mi][0]), "r"(af[mi][1]), "r"(af[mi][2]), "r"(af[mi][3]),
                          "r"(bf[np][1]), "r"(bf[np][3]));
                }
            }
        }
    }

    // ---- store raw tile ----
    const int r0 = mBase + wm + (lane >> 2);
    const int c0 = nBase + wn + (lane & 3) * 2;
#pragma unroll
    for (int mi = 0; mi < 4; ++mi) {
#pragma unroll
        for (int ni = 0; ni < 4; ++ni) {
            const int r = r0 + mi * 16;
            const int c = c0 + ni * 8;
            *(float2*)(out + (size_t)r * HIDDEN + c)       = make_float2(acc[mi][ni][0], acc[mi][ni][1]);
            *(float2*)(out + (size_t)(r + 8) * HIDDEN + c) = make_float2(acc[mi][ni][2], acc[mi][ni][3]);
        }
    }

    // ---- fused row-block RMS-norm: last-arriving CTA of this blockIdx.y ----
    __threadfence();
    __syncthreads();
    __shared__ int s_last;
    if (tid == 0) s_last = (atomicAdd(&g_cnt[blockIdx.y], 1) == 7);
    __syncthreads();
    if (!s_last) return;
    __threadfence();   // acquire: make peers' out-writes visible

    const int row  = tid >> 1;          // 0..127
    const int half = tid & 1;           // 0..1  (512 cols each)
    float4* rowp = (float4*)(out + (size_t)(mBase + row) * HIDDEN + half * 512);
    const float4* nwp = (const float4*)nw + half * 128;

    float ssq = 0.0f;
#pragma unroll 8
    for (int i = 0; i < 128; ++i) {
        float4 v = rowp[i];
        ssq += v.x * v.x + v.y * v.y + v.z * v.z + v.w * v.w;
    }
    ssq += __shfl_xor_sync(0xFFFFFFFFu, ssq, 1);      // combine the two halves
    const float sc = 32.0f * rsqrtf(ssq + 1.024e-3f); // sqrt(H)/sqrt(ssq+EPS*H)

#pragma unroll 8
    for (int i = 0; i < 128; ++i) {
        float4 v = rowp[i];
        float4 w = nwp[i];
        v.x *= sc * w.x; v.y *= sc * w.y; v.z *= sc * w.z; v.w *= sc * w.w;
        rowp[i] = v;
    }
}

// ---------------------------------------------------------------------------
extern "C" void kernel_launch(void* const* d_in, const int* in_sizes, int n_in,
                              void* d_out, int out_size) {
    const float* x  = (const float*)d_in[0];   // [2,4096,1024] fp32
    const float* cw = (const float*)d_in[1];   // [20,1024,1024] fp32
    const float* nw = (const float*)d_in[2];   // [1024] fp32
    float* out = (float*)d_out;                // [2,4096,1024] fp32
    (void)in_sizes; (void)n_in; (void)out_size;

    prep_kernel<<<M_TOTAL*HIDDEN/1024 + HIDDEN*HIDDEN/1024, 256>>>(x, cw);   // 9216 blocks

    cudaFuncSetAttribute(gemm_kernel, cudaFuncAttributeMaxDynamicSharedMemorySize, SMEM_BYTES);
    dim3 grid(HIDDEN / BN, M_TOTAL / BM);   // (8, 64) = 512 CTAs
    gemm_kernel<<<grid, 256, SMEM_BYTES>>>(out, nw);
}

// round 9
// speedup vs baseline: 2.2545x; 2.2545x over previous
#include <cuda_runtime.h>
#include <cuda_fp16.h>
#include <cstdint>

#define HIDDEN   1024
#define NLAYERS  20
#define M_TOTAL  8192

// ---- GEMM tiling (fp16 HMMA m16n8k16) ----
#define BM 128
#define BN 128
#define BKH 64                    // K per tile, in halves -> 128B smem rows
#define KT (HIDDEN/BKH)           // 16
#define ROWB 128
#define A_STAGE (BM*ROWB)         // 16384 B
#define B_STAGE (BN*ROWB)         // 16384 B
#define STAGE   (A_STAGE+B_STAGE) // 32768 B
#define STAGES  3
#define SMEM_BYTES (STAGES*STAGE) // 98304 B -> 2 CTAs/SM

__device__ __half g_wsum[HIDDEN*HIDDEN];     // 2 MB  (pre-summed weights, fp16)
__device__ __half g_ax[M_TOTAL*HIDDEN];      // 16 MB (activations, fp16)

// ---------------------------------------------------------------------------
__device__ __forceinline__ uint32_t smem_u32(const void* p) {
    uint32_t a;
    asm("{ .reg .u64 t; cvta.to.shared.u64 t, %1; cvt.u32.u64 %0, t; }" : "=r"(a) : "l"(p));
    return a;
}
__device__ __forceinline__ void cp16(uint32_t saddr, const void* g) {
    asm volatile("cp.async.cg.shared.global [%0], [%1], 16;" :: "r"(saddr), "l"(g));
}
__device__ __forceinline__ uint32_t f2_to_h2(float lo, float hi) {
    uint32_t r;
    asm("cvt.rn.f16x2.f32 %0, %1, %2;" : "=r"(r) : "f"(hi), "f"(lo));
    return r;
}
// streaming (evict-first) float4 load for read-once data
__device__ __forceinline__ float4 ldcs4(const float4* p) {
    float4 v;
    asm volatile("ld.global.cs.v4.f32 {%0,%1,%2,%3}, [%4];"
                 : "=f"(v.x), "=f"(v.y), "=f"(v.z), "=f"(v.w) : "l"(p));
    return v;
}

// ---------------------------------------------------------------------------
// Kernel 0 (fused prep):
//   blocks [0, 8192):    g_ax  = fp16(x)                 (48 MB, x streamed)
//   blocks [8192, 9216): g_wsum = fp16(mean_l conv_w[l]) (82 MB, cw streamed)
// ---------------------------------------------------------------------------
__global__ void __launch_bounds__(256)
prep_kernel(const float* __restrict__ x, const float* __restrict__ cw) {
    const int b = blockIdx.x, t = threadIdx.x;
    if (b < M_TOTAL * HIDDEN / 1024) {
        const int i4 = b * 256 + t;                    // float4 index
        float4 v = ldcs4(&((const float4*)x)[i4]);
        uint2 h;
        h.x = f2_to_h2(v.x, v.y);
        h.y = f2_to_h2(v.z, v.w);
        ((uint2*)g_ax)[i4] = h;
    } else {
        const int i4 = (b - M_TOTAL * HIDDEN / 1024) * 256 + t;   // 0..262143
        const float4* cw4 = (const float4*)cw;
        float4 a0 = ldcs4(&cw4[i4]);
        float4 a1 = ldcs4(&cw4[(HIDDEN*HIDDEN/4) + i4]);
#pragma unroll
        for (int l = 2; l < NLAYERS; l += 2) {
            float4 v0 = ldcs4(&cw4[l       * (HIDDEN*HIDDEN/4) + i4]);
            float4 v1 = ldcs4(&cw4[(l + 1) * (HIDDEN*HIDDEN/4) + i4]);
            a0.x += v0.x; a0.y += v0.y; a0.z += v0.z; a0.w += v0.w;
            a1.x += v1.x; a1.y += v1.y; a1.z += v1.z; a1.w += v1.w;
        }
        const float s = 1.0f / (float)NLAYERS;
        uint2 h;
        h.x = f2_to_h2((a0.x + a1.x) * s, (a0.y + a1.y) * s);
        h.y = f2_to_h2((a0.z + a1.z) * s, (a0.w + a1.w) * s);
        ((uint2*)g_wsum)[i4] = h;
    }
}

// ---------------------------------------------------------------------------
// Kernel 1: fp16 GEMM  out[m][n] = sum_k Ax[m][k] * Wsum[n][k]
//   (byte-identical to the proven 62us R3 mainloop)
// ---------------------------------------------------------------------------
__global__ void __launch_bounds__(256, 2)
gemm_kernel(float* __restrict__ out) {
    extern __shared__ char smem[];
    const uint32_t sbase = smem_u32(smem);

    const int tid  = threadIdx.x;
    const int lane = tid & 31;
    const int warp = tid >> 5;
    const int wm   = (warp & 1) * 64;
    const int wn   = (warp >> 1) * 32;
    const int mBase = blockIdx.y * BM;
    const int nBase = blockIdx.x * BN;

    float acc[4][4][4];
#pragma unroll
    for (int mi = 0; mi < 4; ++mi)
#pragma unroll
        for (int ni = 0; ni < 4; ++ni)
#pragma unroll
            for (int c = 0; c < 4; ++c) acc[mi][ni][c] = 0.0f;

    auto load_stage = [&](int s, int k0h) {
        const uint32_t sa = sbase + (uint32_t)s * STAGE;
        const uint32_t sb = sa + A_STAGE;
#pragma unroll
        for (int i = 0; i < 4; ++i) {
            const int c = i * 256 + tid;          // 0..1023
            const int row = c >> 3, ch = c & 7;
            const uint32_t off = (uint32_t)c * 16u;
            cp16(sa + (off ^ ((off >> 3) & 0x70u)),
                 g_ax + (size_t)(mBase + row) * HIDDEN + k0h + ch * 8);
        }
#pragma unroll
        for (int i = 0; i < 4; ++i) {
            const int c = i * 256 + tid;
            const int row = c >> 3, ch = c & 7;
            const uint32_t off = (uint32_t)c * 16u;
            cp16(sb + (off ^ ((off >> 3) & 0x70u)),
                 g_wsum + (size_t)(nBase + row) * HIDDEN + k0h + ch * 8);
        }
        asm volatile("cp.async.commit_group;");
    };

    load_stage(0, 0);
    load_stage(1, BKH);

    for (int kt = 0; kt < KT; ++kt) {
        asm volatile("cp.async.wait_group 1;");
        __syncthreads();
        if (kt + 2 < KT) load_stage((kt + 2) % STAGES, (kt + 2) * BKH);
        else             asm volatile("cp.async.commit_group;");

        const uint32_t sa = sbase + (uint32_t)(kt % STAGES) * STAGE;
        const uint32_t sb = sa + A_STAGE;

#pragma unroll
        for (int kk = 0; kk < 4; ++kk) {
            const uint32_t colb = (uint32_t)(kk * 32 + (lane >> 4) * 16);
            uint32_t af[4][4], bf[2][4];
#pragma unroll
            for (int mi = 0; mi < 4; ++mi) {
                const uint32_t off = (uint32_t)(wm + mi * 16 + (lane & 15)) * ROWB + colb;
                const uint32_t addr = sa + (off ^ ((off >> 3) & 0x70u));
                asm volatile("ldmatrix.sync.aligned.m8n8.x4.shared.b16 {%0,%1,%2,%3}, [%4];"
                             : "=r"(af[mi][0]), "=r"(af[mi][1]), "=r"(af[mi][2]), "=r"(af[mi][3])
                             : "r"(addr));
            }
#pragma unroll
            for (int np = 0; np < 2; ++np) {
                const uint32_t off = (uint32_t)(wn + np * 16 + (lane & 15)) * ROWB + colb;
                const uint32_t addr = sb + (off ^ ((off >> 3) & 0x70u));
                asm volatile("ldmatrix.sync.aligned.m8n8.x4.shared.b16 {%0,%1,%2,%3}, [%4];"
                             : "=r"(bf[np][0]), "=r"(bf[np][1]), "=r"(bf[np][2]), "=r"(bf[np][3])
                             : "r"(addr));
            }
#pragma unroll
            for (int mi = 0; mi < 4; ++mi) {
#pragma unroll
                for (int np = 0; np < 2; ++np) {
                    asm volatile(
                        "mma.sync.aligned.m16n8k16.row.col.f32.f16.f16.f32 "
                        "{%0,%1,%2,%3}, {%4,%5,%6,%7}, {%8,%9}, {%0,%1,%2,%3};"
                        : "+f"(acc[mi][np*2][0]), "+f"(acc[mi][np*2][1]),
                          "+f"(acc[mi][np*2][2]), "+f"(acc[mi][np*2][3])
                        : "r"(af[mi][0]), "r"(af[mi][1]), "r"(af[mi][2]), "r"(af[mi][3]),
                          "r"(bf[np][0]), "r"(bf[np][2]));
                    asm volatile(
                        "mma.sync.aligned.m16n8k16.row.col.f32.f16.f16.f32 "
                        "{%0,%1,%2,%3}, {%4,%5,%6,%7}, {%8,%9}, {%0,%1,%2,%3};"
                        : "+f"(acc[mi][np*2+1][0]), "+f"(acc[mi][np*2+1][1]),
                          "+f"(acc[mi][np*2+1][2]), "+f"(acc[mi][np*2+1][3])
                        : "r"(af[mi][0]), "r"(af[mi][1]), "r"(af[mi][2]), "r"(af[mi][3]),
                          "r"(bf[np][1]), "r"(bf[np][3]));
                }
            }
        }
    }

    // epilogue
    const int r0 = mBase + wm + (lane >> 2);
    const int c0 = nBase + wn + (lane & 3) * 2;
#pragma unroll
    for (int mi = 0; mi < 4; ++mi) {
#pragma unroll
        for (int ni = 0; ni < 4; ++ni) {
            const int r = r0 + mi * 16;
            const int c = c0 + ni * 8;
            *(float2*)(out + (size_t)r * HIDDEN + c)       = make_float2(acc[mi][ni][0], acc[mi][ni][1]);
            *(float2*)(out + (size_t)(r + 8) * HIDDEN + c) = make_float2(acc[mi][ni][2], acc[mi][ni][3]);
        }
    }
}

// ---------------------------------------------------------------------------
// Kernel 2: in-place RMS-norm:  x * sqrt(H) / sqrt(sum x^2 + EPS*H) * w
// ---------------------------------------------------------------------------
__global__ void __launch_bounds__(256)
rmsnorm_kernel(float* __restrict__ out, const float* __restrict__ nw) {
    const int row = blockIdx.x;
    float4* p = (float4*)(out + (size_t)row * HIDDEN);
    float4 v = p[threadIdx.x];

    float ss = v.x * v.x + v.y * v.y + v.z * v.z + v.w * v.w;
#pragma unroll
    for (int o = 16; o > 0; o >>= 1) ss += __shfl_xor_sync(0xFFFFFFFFu, ss, o);

    __shared__ float wsum[8];
    __shared__ float s_scale;
    if ((threadIdx.x & 31) == 0) wsum[threadIdx.x >> 5] = ss;
    __syncthreads();
    if (threadIdx.x == 0) {
        float t = 0.0f;
#pragma unroll
        for (int i = 0; i < 8; ++i) t += wsum[i];
        s_scale = 32.0f * rsqrtf(t + 1.024e-3f);
    }
    __syncthreads();
    const float sc = s_scale;

    float4 w = ((const float4*)nw)[threadIdx.x];
    v.x = v.x * sc * w.x;
    v.y = v.y * sc * w.y;
    v.z = v.z * sc * w.z;
    v.w = v.w * sc * w.w;
    p[threadIdx.x] = v;
}

// ---------------------------------------------------------------------------
extern "C" void kernel_launch(void* const* d_in, const int* in_sizes, int n_in,
                              void* d_out, int out_size) {
    const float* x  = (const float*)d_in[0];   // [2,4096,1024] fp32
    const float* cw = (const float*)d_in[1];   // [20,1024,1024] fp32
    const float* nw = (const float*)d_in[2];   // [1024] fp32
    float* out = (float*)d_out;                // [2,4096,1024] fp32
    (void)in_sizes; (void)n_in; (void)out_size;

    prep_kernel<<<M_TOTAL*HIDDEN/1024 + HIDDEN*HIDDEN/1024, 256>>>(x, cw);   // 9216 blocks

    cudaFuncSetAttribute(gemm_kernel, cudaFuncAttributeMaxDynamicSharedMemorySize, SMEM_BYTES);
    dim3 grid(HIDDEN / BN, M_TOTAL / BM);   // (8, 64) = 512 CTAs
    gemm_kernel<<<grid, 256, SMEM_BYTES>>>(out);

    rmsnorm_kernel<<<M_TOTAL, 256>>>(out, nw);
}

// round 10
// speedup vs baseline: 2.3506x; 1.0426x over previous
#include <cuda_runtime.h>
#include <cuda_fp16.h>
#include <cstdint>

#define HIDDEN   1024
#define NLAYERS  20
#define M_TOTAL  8192

// ---- GEMM tiling (fp16 HMMA m16n8k16) ----
#define BM 128
#define BN 128
#define BKH 64                    // K per tile, in halves -> 128B smem rows
#define KT (HIDDEN/BKH)           // 16
#define ROWB 128
#define A_STAGE (BM*ROWB)         // 16384 B
#define B_STAGE (BN*ROWB)         // 16384 B
#define STAGE   (A_STAGE+B_STAGE) // 32768 B
#define STAGES  3
#define SMEM_BYTES (STAGES*STAGE) // 98304 B -> 2 CTAs/SM

#define WSUM_BLOCKS (HIDDEN*HIDDEN/1024)        // 1024
#define X_BLOCKS    (M_TOTAL*HIDDEN/4096)       // 2048 (4 float4 per thread)

__device__ __half g_wsum[HIDDEN*HIDDEN];     // 2 MB  (pre-summed weights, fp16)
__device__ __half g_ax[M_TOTAL*HIDDEN];      // 16 MB (activations, fp16)

// ---------------------------------------------------------------------------
__device__ __forceinline__ uint32_t smem_u32(const void* p) {
    uint32_t a;
    asm("{ .reg .u64 t; cvta.to.shared.u64 t, %1; cvt.u32.u64 %0, t; }" : "=r"(a) : "l"(p));
    return a;
}
__device__ __forceinline__ void cp16(uint32_t saddr, const void* g) {
    asm volatile("cp.async.cg.shared.global [%0], [%1], 16;" :: "r"(saddr), "l"(g));
}
__device__ __forceinline__ uint32_t f2_to_h2(float lo, float hi) {
    uint32_t r;
    asm("cvt.rn.f16x2.f32 %0, %1, %2;" : "=r"(r) : "f"(hi), "f"(lo));
    return r;
}
// streaming (evict-first) float4 load for read-once data
__device__ __forceinline__ float4 ldcs4(const float4* p) {
    float4 v;
    asm volatile("ld.global.cs.v4.f32 {%0,%1,%2,%3}, [%4];"
                 : "=f"(v.x), "=f"(v.y), "=f"(v.z), "=f"(v.w) : "l"(p));
    return v;
}

// ---------------------------------------------------------------------------
// Kernel 0 (fused prep):
//   blocks [0, 1024):    g_wsum = fp16(mean_l conv_w[l])   (long blocks first)
//   blocks [1024, 3072): g_ax  = fp16(x), 4 float4/thread  (MLP=4)
// ---------------------------------------------------------------------------
__global__ void __launch_bounds__(256)
prep_kernel(const float* __restrict__ x, const float* __restrict__ cw) {
    const int b = blockIdx.x, t = threadIdx.x;
    if (b < WSUM_BLOCKS) {
        const int i4 = b * 256 + t;                    // 0..262143
        const float4* cw4 = (const float4*)cw;
        float4 a0 = ldcs4(&cw4[i4]);
        float4 a1 = ldcs4(&cw4[(HIDDEN*HIDDEN/4) + i4]);
#pragma unroll
        for (int l = 2; l < NLAYERS; l += 2) {
            float4 v0 = ldcs4(&cw4[l       * (HIDDEN*HIDDEN/4) + i4]);
            float4 v1 = ldcs4(&cw4[(l + 1) * (HIDDEN*HIDDEN/4) + i4]);
            a0.x += v0.x; a0.y += v0.y; a0.z += v0.z; a0.w += v0.w;
            a1.x += v1.x; a1.y += v1.y; a1.z += v1.z; a1.w += v1.w;
        }
        const float s = 1.0f / (float)NLAYERS;
        uint2 h;
        h.x = f2_to_h2((a0.x + a1.x) * s, (a0.y + a1.y) * s);
        h.y = f2_to_h2((a0.z + a1.z) * s, (a0.w + a1.w) * s);
        ((uint2*)g_wsum)[i4] = h;
    } else {
        // 4 independent float4 per thread (front-batched -> MLP=4)
        const int base = (b - WSUM_BLOCKS) * 1024 + t;   // float4 index base
        float4 v[4];
#pragma unroll
        for (int i = 0; i < 4; ++i)
            v[i] = ldcs4(&((const float4*)x)[base + i * 256]);
#pragma unroll
        for (int i = 0; i < 4; ++i) {
            uint2 h;
            h.x = f2_to_h2(v[i].x, v[i].y);
            h.y = f2_to_h2(v[i].z, v[i].w);
            ((uint2*)g_ax)[base + i * 256] = h;
        }
    }
}

// ---------------------------------------------------------------------------
// Kernel 1: fp16 GEMM  out[m][n] = sum_k Ax[m][k] * Wsum[n][k]
//   (byte-identical to the proven 62us R3 mainloop)
// ---------------------------------------------------------------------------
__global__ void __launch_bounds__(256, 2)
gemm_kernel(float* __restrict__ out) {
    extern __shared__ char smem[];
    const uint32_t sbase = smem_u32(smem);

    const int tid  = threadIdx.x;
    const int lane = tid & 31;
    const int warp = tid >> 5;
    const int wm   = (warp & 1) * 64;
    const int wn   = (warp >> 1) * 32;
    const int mBase = blockIdx.y * BM;
    const int nBase = blockIdx.x * BN;

    float acc[4][4][4];
#pragma unroll
    for (int mi = 0; mi < 4; ++mi)
#pragma unroll
        for (int ni = 0; ni < 4; ++ni)
#pragma unroll
            for (int c = 0; c < 4; ++c) acc[mi][ni][c] = 0.0f;

    auto load_stage = [&](int s, int k0h) {
        const uint32_t sa = sbase + (uint32_t)s * STAGE;
        const uint32_t sb = sa + A_STAGE;
#pragma unroll
        for (int i = 0; i < 4; ++i) {
            const int c = i * 256 + tid;          // 0..1023
            const int row = c >> 3, ch = c & 7;
            const uint32_t off = (uint32_t)c * 16u;
            cp16(sa + (off ^ ((off >> 3) & 0x70u)),
                 g_ax + (size_t)(mBase + row) * HIDDEN + k0h + ch * 8);
        }
#pragma unroll
        for (int i = 0; i < 4; ++i) {
            const int c = i * 256 + tid;
            const int row = c >> 3, ch = c & 7;
            const uint32_t off = (uint32_t)c * 16u;
            cp16(sb + (off ^ ((off >> 3) & 0x70u)),
                 g_wsum + (size_t)(nBase + row) * HIDDEN + k0h + ch * 8);
        }
        asm volatile("cp.async.commit_group;");
    };

    load_stage(0, 0);
    load_stage(1, BKH);

    for (int kt = 0; kt < KT; ++kt) {
        asm volatile("cp.async.wait_group 1;");
        __syncthreads();
        if (kt + 2 < KT) load_stage((kt + 2) % STAGES, (kt + 2) * BKH);
        else             asm volatile("cp.async.commit_group;");

        const uint32_t sa = sbase + (uint32_t)(kt % STAGES) * STAGE;
        const uint32_t sb = sa + A_STAGE;

#pragma unroll
        for (int kk = 0; kk < 4; ++kk) {
            const uint32_t colb = (uint32_t)(kk * 32 + (lane >> 4) * 16);
            uint32_t af[4][4], bf[2][4];
#pragma unroll
            for (int mi = 0; mi < 4; ++mi) {
                const uint32_t off = (uint32_t)(wm + mi * 16 + (lane & 15)) * ROWB + colb;
                const uint32_t addr = sa + (off ^ ((off >> 3) & 0x70u));
                asm volatile("ldmatrix.sync.aligned.m8n8.x4.shared.b16 {%0,%1,%2,%3}, [%4];"
                             : "=r"(af[mi][0]), "=r"(af[mi][1]), "=r"(af[mi][2]), "=r"(af[mi][3])
                             : "r"(addr));
            }
#pragma unroll
            for (int np = 0; np < 2; ++np) {
                const uint32_t off = (uint32_t)(wn + np * 16 + (lane & 15)) * ROWB + colb;
                const uint32_t addr = sb + (off ^ ((off >> 3) & 0x70u));
                asm volatile("ldmatrix.sync.aligned.m8n8.x4.shared.b16 {%0,%1,%2,%3}, [%4];"
                             : "=r"(bf[np][0]), "=r"(bf[np][1]), "=r"(bf[np][2]), "=r"(bf[np][3])
                             : "r"(addr));
            }
#pragma unroll
            for (int mi = 0; mi < 4; ++mi) {
#pragma unroll
                for (int np = 0; np < 2; ++np) {
                    asm volatile(
                        "mma.sync.aligned.m16n8k16.row.col.f32.f16.f16.f32 "
                        "{%0,%1,%2,%3}, {%4,%5,%6,%7}, {%8,%9}, {%0,%1,%2,%3};"
                        : "+f"(acc[mi][np*2][0]), "+f"(acc[mi][np*2][1]),
                          "+f"(acc[mi][np*2][2]), "+f"(acc[mi][np*2][3])
                        : "r"(af[mi][0]), "r"(af[mi][1]), "r"(af[mi][2]), "r"(af[mi][3]),
                          "r"(bf[np][0]), "r"(bf[np][2]));
                    asm volatile(
                        "mma.sync.aligned.m16n8k16.row.col.f32.f16.f16.f32 "
                        "{%0,%1,%2,%3}, {%4,%5,%6,%7}, {%8,%9}, {%0,%1,%2,%3};"
                        : "+f"(acc[mi][np*2+1][0]), "+f"(acc[mi][np*2+1][1]),
                          "+f"(acc[mi][np*2+1][2]), "+f"(acc[mi][np*2+1][3])
                        : "r"(af[mi][0]), "r"(af[mi][1]), "r"(af[mi][2]), "r"(af[mi][3]),
                          "r"(bf[np][1]), "r"(bf[np][3]));
                }
            }
        }
    }

    // epilogue
    const int r0 = mBase + wm + (lane >> 2);
    const int c0 = nBase + wn + (lane & 3) * 2;
#pragma unroll
    for (int mi = 0; mi < 4; ++mi) {
#pragma unroll
        for (int ni = 0; ni < 4; ++ni) {
            const int r = r0 + mi * 16;
            const int c = c0 + ni * 8;
            *(float2*)(out + (size_t)r * HIDDEN + c)       = make_float2(acc[mi][ni][0], acc[mi][ni][1]);
            *(float2*)(out + (size_t)(r + 8) * HIDDEN + c) = make_float2(acc[mi][ni][2], acc[mi][ni][3]);
        }
    }
}

// ---------------------------------------------------------------------------
// Kernel 2: in-place RMS-norm:  x * sqrt(H) / sqrt(sum x^2 + EPS*H) * w
// ---------------------------------------------------------------------------
__global__ void __launch_bounds__(256)
rmsnorm_kernel(float* __restrict__ out, const float* __restrict__ nw) {
    const int row = blockIdx.x;
    float4* p = (float4*)(out + (size_t)row * HIDDEN);
    float4 v = p[threadIdx.x];

    float ss = v.x * v.x + v.y * v.y + v.z * v.z + v.w * v.w;
#pragma unroll
    for (int o = 16; o > 0; o >>= 1) ss += __shfl_xor_sync(0xFFFFFFFFu, ss, o);

    __shared__ float wsum[8];
    __shared__ float s_scale;
    if ((threadIdx.x & 31) == 0) wsum[threadIdx.x >> 5] = ss;
    __syncthreads();
    if (threadIdx.x == 0) {
        float t = 0.0f;
#pragma unroll
        for (int i = 0; i < 8; ++i) t += wsum[i];
        s_scale = 32.0f * rsqrtf(t + 1.024e-3f);
    }
    __syncthreads();
    const float sc = s_scale;

    float4 w = ((const float4*)nw)[threadIdx.x];
    v.x = v.x * sc * w.x;
    v.y = v.y * sc * w.y;
    v.z = v.z * sc * w.z;
    v.w = v.w * sc * w.w;
    p[threadIdx.x] = v;
}

// ---------------------------------------------------------------------------
extern "C" void kernel_launch(void* const* d_in, const int* in_sizes, int n_in,
                              void* d_out, int out_size) {
    const float* x  = (const float*)d_in[0];   // [2,4096,1024] fp32
    const float* cw = (const float*)d_in[1];   // [20,1024,1024] fp32
    const float* nw = (const float*)d_in[2];   // [1024] fp32
    float* out = (float*)d_out;                // [2,4096,1024] fp32
    (void)in_sizes; (void)n_in; (void)out_size;

    prep_kernel<<<WSUM_BLOCKS + X_BLOCKS, 256>>>(x, cw);   // 3072 blocks

    cudaFuncSetAttribute(gemm_kernel, cudaFuncAttributeMaxDynamicSharedMemorySize, SMEM_BYTES);
    dim3 grid(HIDDEN / BN, M_TOTAL / BM);   // (8, 64) = 512 CTAs
    gemm_kernel<<<grid, 256, SMEM_BYTES>>>(out);

    rmsnorm_kernel<<<M_TOTAL, 256>>>(out, nw);
}

// round 11
// speedup vs baseline: 2.3564x; 1.0025x over previous
#include <cuda_runtime.h>
#include <cuda_fp16.h>
#include <cstdint>

#define HIDDEN   1024
#define NLAYERS  20
#define M_TOTAL  8192

// ---- GEMM tiling (fp16 HMMA m16n8k16) ----
#define BM 128
#define BN 128
#define BKH 64                    // K per tile, in halves -> 128B smem rows
#define KT (HIDDEN/BKH)           // 16
#define ROWB 128
#define A_STAGE (BM*ROWB)         // 16384 B
#define B_STAGE (BN*ROWB)         // 16384 B
#define STAGE   (A_STAGE+B_STAGE) // 32768 B
#define STAGES  3
#define SMEM_BYTES (STAGES*STAGE) // 98304 B -> 2 CTAs/SM

#define WSUM_BLOCKS (HIDDEN*HIDDEN/1024)        // 1024
#define X_BLOCKS    (M_TOTAL*HIDDEN/8192)       // 1024 (8 float4 per thread)

__device__ __half g_wsum[HIDDEN*HIDDEN];     // 2 MB  (pre-summed weights, fp16)
__device__ __half g_ax[M_TOTAL*HIDDEN];      // 16 MB (activations, fp16)

// ---------------------------------------------------------------------------
__device__ __forceinline__ uint32_t smem_u32(const void* p) {
    uint32_t a;
    asm("{ .reg .u64 t; cvta.to.shared.u64 t, %1; cvt.u32.u64 %0, t; }" : "=r"(a) : "l"(p));
    return a;
}
__device__ __forceinline__ void cp16(uint32_t saddr, const void* g) {
    asm volatile("cp.async.cg.shared.global [%0], [%1], 16;" :: "r"(saddr), "l"(g));
}
__device__ __forceinline__ uint32_t f2_to_h2(float lo, float hi) {
    uint32_t r;
    asm("cvt.rn.f16x2.f32 %0, %1, %2;" : "=r"(r) : "f"(hi), "f"(lo));
    return r;
}
// streaming (evict-first) float4 load for read-once data
__device__ __forceinline__ float4 ldcs4(const float4* p) {
    float4 v;
    asm volatile("ld.global.cs.v4.f32 {%0,%1,%2,%3}, [%4];"
                 : "=f"(v.x), "=f"(v.y), "=f"(v.z), "=f"(v.w) : "l"(p));
    return v;
}

// ---------------------------------------------------------------------------
// Kernel 0 (fused prep):
//   blocks [0, 1024):    g_wsum = fp16(mean_l conv_w[l])   (long blocks first)
//   blocks [1024, 2048): g_ax  = fp16(x), 8 float4/thread  (MLP=8)
// ---------------------------------------------------------------------------
__global__ void __launch_bounds__(256)
prep_kernel(const float* __restrict__ x, const float* __restrict__ cw) {
    const int b = blockIdx.x, t = threadIdx.x;
    if (b < WSUM_BLOCKS) {
        const int i4 = b * 256 + t;                    // 0..262143
        const float4* cw4 = (const float4*)cw;
        float4 a0 = ldcs4(&cw4[i4]);
        float4 a1 = ldcs4(&cw4[(HIDDEN*HIDDEN/4) + i4]);
#pragma unroll
        for (int l = 2; l < NLAYERS; l += 2) {
            float4 v0 = ldcs4(&cw4[l       * (HIDDEN*HIDDEN/4) + i4]);
            float4 v1 = ldcs4(&cw4[(l + 1) * (HIDDEN*HIDDEN/4) + i4]);
            a0.x += v0.x; a0.y += v0.y; a0.z += v0.z; a0.w += v0.w;
            a1.x += v1.x; a1.y += v1.y; a1.z += v1.z; a1.w += v1.w;
        }
        const float s = 1.0f / (float)NLAYERS;
        uint2 h;
        h.x = f2_to_h2((a0.x + a1.x) * s, (a0.y + a1.y) * s);
        h.y = f2_to_h2((a0.z + a1.z) * s, (a0.w + a1.w) * s);
        ((uint2*)g_wsum)[i4] = h;
    } else {
        // 8 independent float4 per thread (front-batched -> MLP=8)
        const int base = (b - WSUM_BLOCKS) * 2048 + t;   // float4 index base
        float4 v[8];
#pragma unroll
        for (int i = 0; i < 8; ++i)
            v[i] = ldcs4(&((const float4*)x)[base + i * 256]);
#pragma unroll
        for (int i = 0; i < 8; ++i) {
            uint2 h;
            h.x = f2_to_h2(v[i].x, v[i].y);
            h.y = f2_to_h2(v[i].z, v[i].w);
            ((uint2*)g_ax)[base + i * 256] = h;
        }
    }
}

// ---------------------------------------------------------------------------
// Kernel 1: fp16 GEMM  out[m][n] = sum_k Ax[m][k] * Wsum[n][k]
//   (byte-identical to the proven 62us R3 mainloop)
// ---------------------------------------------------------------------------
__global__ void __launch_bounds__(256, 2)
gemm_kernel(float* __restrict__ out) {
    extern __shared__ char smem[];
    const uint32_t sbase = smem_u32(smem);

    const int tid  = threadIdx.x;
    const int lane = tid & 31;
    const int warp = tid >> 5;
    const int wm   = (warp & 1) * 64;
    const int wn   = (warp >> 1) * 32;
    const int mBase = blockIdx.y * BM;
    const int nBase = blockIdx.x * BN;

    float acc[4][4][4];
#pragma unroll
    for (int mi = 0; mi < 4; ++mi)
#pragma unroll
        for (int ni = 0; ni < 4; ++ni)
#pragma unroll
            for (int c = 0; c < 4; ++c) acc[mi][ni][c] = 0.0f;

    auto load_stage = [&](int s, int k0h) {
        const uint32_t sa = sbase + (uint32_t)s * STAGE;
        const uint32_t sb = sa + A_STAGE;
#pragma unroll
        for (int i = 0; i < 4; ++i) {
            const int c = i * 256 + tid;          // 0..1023
            const int row = c >> 3, ch = c & 7;
            const uint32_t off = (uint32_t)c * 16u;
            cp16(sa + (off ^ ((off >> 3) & 0x70u)),
                 g_ax + (size_t)(mBase + row) * HIDDEN + k0h + ch * 8);
        }
#pragma unroll
        for (int i = 0; i < 4; ++i) {
            const int c = i * 256 + tid;
            const int row = c >> 3, ch = c & 7;
            const uint32_t off = (uint32_t)c * 16u;
            cp16(sb + (off ^ ((off >> 3) & 0x70u)),
                 g_wsum + (size_t)(nBase + row) * HIDDEN + k0h + ch * 8);
        }
        asm volatile("cp.async.commit_group;");
    };

    load_stage(0, 0);
    load_stage(1, BKH);

    for (int kt = 0; kt < KT; ++kt) {
        asm volatile("cp.async.wait_group 1;");
        __syncthreads();
        if (kt + 2 < KT) load_stage((kt + 2) % STAGES, (kt + 2) * BKH);
        else             asm volatile("cp.async.commit_group;");

        const uint32_t sa = sbase + (uint32_t)(kt % STAGES) * STAGE;
        const uint32_t sb = sa + A_STAGE;

#pragma unroll
        for (int kk = 0; kk < 4; ++kk) {
            const uint32_t colb = (uint32_t)(kk * 32 + (lane >> 4) * 16);
            uint32_t af[4][4], bf[2][4];
#pragma unroll
            for (int mi = 0; mi < 4; ++mi) {
                const uint32_t off = (uint32_t)(wm + mi * 16 + (lane & 15)) * ROWB + colb;
                const uint32_t addr = sa + (off ^ ((off >> 3) & 0x70u));
                asm volatile("ldmatrix.sync.aligned.m8n8.x4.shared.b16 {%0,%1,%2,%3}, [%4];"
                             : "=r"(af[mi][0]), "=r"(af[mi][1]), "=r"(af[mi][2]), "=r"(af[mi][3])
                             : "r"(addr));
            }
#pragma unroll
            for (int np = 0; np < 2; ++np) {
                const uint32_t off = (uint32_t)(wn + np * 16 + (lane & 15)) * ROWB + colb;
                const uint32_t addr = sb + (off ^ ((off >> 3) & 0x70u));
                asm volatile("ldmatrix.sync.aligned.m8n8.x4.shared.b16 {%0,%1,%2,%3}, [%4];"
                             : "=r"(bf[np][0]), "=r"(bf[np][1]), "=r"(bf[np][2]), "=r"(bf[np][3])
                             : "r"(addr));
            }
#pragma unroll
            for (int mi = 0; mi < 4; ++mi) {
#pragma unroll
                for (int np = 0; np < 2; ++np) {
                    asm volatile(
                        "mma.sync.aligned.m16n8k16.row.col.f32.f16.f16.f32 "
                        "{%0,%1,%2,%3}, {%4,%5,%6,%7}, {%8,%9}, {%0,%1,%2,%3};"
                        : "+f"(acc[mi][np*2][0]), "+f"(acc[mi][np*2][1]),
                          "+f"(acc[mi][np*2][2]), "+f"(acc[mi][np*2][3])
                        : "r"(af[mi][0]), "r"(af[mi][1]), "r"(af[mi][2]), "r"(af[mi][3]),
                          "r"(bf[np][0]), "r"(bf[np][2]));
                    asm volatile(
                        "mma.sync.aligned.m16n8k16.row.col.f32.f16.f16.f32 "
                        "{%0,%1,%2,%3}, {%4,%5,%6,%7}, {%8,%9}, {%0,%1,%2,%3};"
                        : "+f"(acc[mi][np*2+1][0]), "+f"(acc[mi][np*2+1][1]),
                          "+f"(acc[mi][np*2+1][2]), "+f"(acc[mi][np*2+1][3])
                        : "r"(af[mi][0]), "r"(af[mi][1]), "r"(af[mi][2]), "r"(af[mi][3]),
                          "r"(bf[np][1]), "r"(bf[np][3]));
                }
            }
        }
    }

    // epilogue
    const int r0 = mBase + wm + (lane >> 2);
    const int c0 = nBase + wn + (lane & 3) * 2;
#pragma unroll
    for (int mi = 0; mi < 4; ++mi) {
#pragma unroll
        for (int ni = 0; ni < 4; ++ni) {
            const int r = r0 + mi * 16;
            const int c = c0 + ni * 8;
            *(float2*)(out + (size_t)r * HIDDEN + c)       = make_float2(acc[mi][ni][0], acc[mi][ni][1]);
            *(float2*)(out + (size_t)(r + 8) * HIDDEN + c) = make_float2(acc[mi][ni][2], acc[mi][ni][3]);
        }
    }
}

// ---------------------------------------------------------------------------
// Kernel 2: in-place RMS-norm:  x * sqrt(H) / sqrt(sum x^2 + EPS*H) * w
// ---------------------------------------------------------------------------
__global__ void __launch_bounds__(256)
rmsnorm_kernel(float* __restrict__ out, const float* __restrict__ nw) {
    const int row = blockIdx.x;
    float4* p = (float4*)(out + (size_t)row * HIDDEN);
    float4 v = p[threadIdx.x];

    float ss = v.x * v.x + v.y * v.y + v.z * v.z + v.w * v.w;
#pragma unroll
    for (int o = 16; o > 0; o >>= 1) ss += __shfl_xor_sync(0xFFFFFFFFu, ss, o);

    __shared__ float wsum[8];
    __shared__ float s_scale;
    if ((threadIdx.x & 31) == 0) wsum[threadIdx.x >> 5] = ss;
    __syncthreads();
    if (threadIdx.x == 0) {
        float t = 0.0f;
#pragma unroll
        for (int i = 0; i < 8; ++i) t += wsum[i];
        s_scale = 32.0f * rsqrtf(t + 1.024e-3f);
    }
    __syncthreads();
    const float sc = s_scale;

    float4 w = ((const float4*)nw)[threadIdx.x];
    v.x = v.x * sc * w.x;
    v.y = v.y * sc * w.y;
    v.z = v.z * sc * w.z;
    v.w = v.w * sc * w.w;
    p[threadIdx.x] = v;
}

// ---------------------------------------------------------------------------
extern "C" void kernel_launch(void* const* d_in, const int* in_sizes, int n_in,
                              void* d_out, int out_size) {
    const float* x  = (const float*)d_in[0];   // [2,4096,1024] fp32
    const float* cw = (const float*)d_in[1];   // [20,1024,1024] fp32
    const float* nw = (const float*)d_in[2];   // [1024] fp32
    float* out = (float*)d_out;                // [2,4096,1024] fp32
    (void)in_sizes; (void)n_in; (void)out_size;

    prep_kernel<<<WSUM_BLOCKS + X_BLOCKS, 256>>>(x, cw);   // 2048 blocks

    cudaFuncSetAttribute(gemm_kernel, cudaFuncAttributeMaxDynamicSharedMemorySize, SMEM_BYTES);
    dim3 grid(HIDDEN / BN, M_TOTAL / BM);   // (8, 64) = 512 CTAs
    gemm_kernel<<<grid, 256, SMEM_BYTES>>>(out);

    rmsnorm_kernel<<<M_TOTAL, 256>>>(out, nw);
}

// round 12
// speedup vs baseline: 2.3681x; 1.0050x over previous
#include <cuda_runtime.h>
#include <cuda_fp16.h>
#include <cstdint>

#define HIDDEN   1024
#define NLAYERS  20
#define M_TOTAL  8192

// ---- GEMM tiling (fp16 HMMA m16n8k16) ----
#define BM 128
#define BN 128
#define BKH 64                    // K per tile, in halves -> 128B smem rows
#define KT (HIDDEN/BKH)           // 16
#define ROWB 128
#define A_STAGE (BM*ROWB)         // 16384 B
#define B_STAGE (BN*ROWB)         // 16384 B
#define STAGE   (A_STAGE+B_STAGE) // 32768 B
#define STAGES  3
#define SMEM_BYTES (STAGES*STAGE) // 98304 B -> 2 CTAs/SM

#define WSUM_BLOCKS (HIDDEN*HIDDEN/1024)        // 1024
#define X_BLOCKS    (M_TOTAL*HIDDEN/8192)       // 1024 (8 float4 per thread)

__device__ __half g_wsum[HIDDEN*HIDDEN];     // 2 MB  (pre-summed weights, fp16)
__device__ __half g_ax[M_TOTAL*HIDDEN];      // 16 MB (activations, fp16)

// ---------------------------------------------------------------------------
__device__ __forceinline__ uint32_t smem_u32(const void* p) {
    uint32_t a;
    asm("{ .reg .u64 t; cvta.to.shared.u64 t, %1; cvt.u32.u64 %0, t; }" : "=r"(a) : "l"(p));
    return a;
}
__device__ __forceinline__ void cp16(uint32_t saddr, const void* g) {
    asm volatile("cp.async.cg.shared.global [%0], [%1], 16;" :: "r"(saddr), "l"(g));
}
__device__ __forceinline__ uint32_t f2_to_h2(float lo, float hi) {
    uint32_t r;
    asm("cvt.rn.f16x2.f32 %0, %1, %2;" : "=r"(r) : "f"(hi), "f"(lo));
    return r;
}
// streaming (evict-first) float4 load for read-once data
__device__ __forceinline__ float4 ldcs4(const float4* p) {
    float4 v;
    asm volatile("ld.global.cs.v4.f32 {%0,%1,%2,%3}, [%4];"
                 : "=f"(v.x), "=f"(v.y), "=f"(v.z), "=f"(v.w) : "l"(p));
    return v;
}

// ---------------------------------------------------------------------------
// Kernel 0 (fused prep):
//   blocks [0, 1024):    g_wsum = fp16(mean_l conv_w[l])   (long blocks first)
//   blocks [1024, 2048): g_ax  = fp16(x), 8 float4/thread  (MLP=8)
// ---------------------------------------------------------------------------
__global__ void __launch_bounds__(256)
prep_kernel(const float* __restrict__ x, const float* __restrict__ cw) {
    const int b = blockIdx.x, t = threadIdx.x;
    if (b < WSUM_BLOCKS) {
        const int i4 = b * 256 + t;                    // 0..262143
        const float4* cw4 = (const float4*)cw;
        float4 a0 = ldcs4(&cw4[i4]);
        float4 a1 = ldcs4(&cw4[(HIDDEN*HIDDEN/4) + i4]);
#pragma unroll
        for (int l = 2; l < NLAYERS; l += 2) {
            float4 v0 = ldcs4(&cw4[l       * (HIDDEN*HIDDEN/4) + i4]);
            float4 v1 = ldcs4(&cw4[(l + 1) * (HIDDEN*HIDDEN/4) + i4]);
            a0.x += v0.x; a0.y += v0.y; a0.z += v0.z; a0.w += v0.w;
            a1.x += v1.x; a1.y += v1.y; a1.z += v1.z; a1.w += v1.w;
        }
        const float s = 1.0f / (float)NLAYERS;
        uint2 h;
        h.x = f2_to_h2((a0.x + a1.x) * s, (a0.y + a1.y) * s);
        h.y = f2_to_h2((a0.z + a1.z) * s, (a0.w + a1.w) * s);
        ((uint2*)g_wsum)[i4] = h;
    } else {
        // 8 independent float4 per thread (front-batched -> MLP=8)
        const int base = (b - WSUM_BLOCKS) * 2048 + t;   // float4 index base
        float4 v[8];
#pragma unroll
        for (int i = 0; i < 8; ++i)
            v[i] = ldcs4(&((const float4*)x)[base + i * 256]);
#pragma unroll
        for (int i = 0; i < 8; ++i) {
            uint2 h;
            h.x = f2_to_h2(v[i].x, v[i].y);
            h.y = f2_to_h2(v[i].z, v[i].w);
            ((uint2*)g_ax)[base + i * 256] = h;
        }
    }
}

// ---------------------------------------------------------------------------
// Kernel 1: fp16 GEMM  out[m][n] = sum_k Ax[m][k] * Wsum[n][k]
//   (byte-identical to the proven 62us R3 mainloop)
// ---------------------------------------------------------------------------
__global__ void __launch_bounds__(256, 2)
gemm_kernel(float* __restrict__ out) {
    extern __shared__ char smem[];
    const uint32_t sbase = smem_u32(smem);

    const int tid  = threadIdx.x;
    const int lane = tid & 31;
    const int warp = tid >> 5;
    const int wm   = (warp & 1) * 64;
    const int wn   = (warp >> 1) * 32;
    const int mBase = blockIdx.y * BM;
    const int nBase = blockIdx.x * BN;

    float acc[4][4][4];
#pragma unroll
    for (int mi = 0; mi < 4; ++mi)
#pragma unroll
        for (int ni = 0; ni < 4; ++ni)
#pragma unroll
            for (int c = 0; c < 4; ++c) acc[mi][ni][c] = 0.0f;

    auto load_stage = [&](int s, int k0h) {
        const uint32_t sa = sbase + (uint32_t)s * STAGE;
        const uint32_t sb = sa + A_STAGE;
#pragma unroll
        for (int i = 0; i < 4; ++i) {
            const int c = i * 256 + tid;          // 0..1023
            const int row = c >> 3, ch = c & 7;
            const uint32_t off = (uint32_t)c * 16u;
            cp16(sa + (off ^ ((off >> 3) & 0x70u)),
                 g_ax + (size_t)(mBase + row) * HIDDEN + k0h + ch * 8);
        }
#pragma unroll
        for (int i = 0; i < 4; ++i) {
            const int c = i * 256 + tid;
            const int row = c >> 3, ch = c & 7;
            const uint32_t off = (uint32_t)c * 16u;
            cp16(sb + (off ^ ((off >> 3) & 0x70u)),
                 g_wsum + (size_t)(nBase + row) * HIDDEN + k0h + ch * 8);
        }
        asm volatile("cp.async.commit_group;");
    };

    load_stage(0, 0);
    load_stage(1, BKH);

    for (int kt = 0; kt < KT; ++kt) {
        asm volatile("cp.async.wait_group 1;");
        __syncthreads();
        if (kt + 2 < KT) load_stage((kt + 2) % STAGES, (kt + 2) * BKH);
        else             asm volatile("cp.async.commit_group;");

        const uint32_t sa = sbase + (uint32_t)(kt % STAGES) * STAGE;
        const uint32_t sb = sa + A_STAGE;

#pragma unroll
        for (int kk = 0; kk < 4; ++kk) {
            const uint32_t colb = (uint32_t)(kk * 32 + (lane >> 4) * 16);
            uint32_t af[4][4], bf[2][4];
#pragma unroll
            for (int mi = 0; mi < 4; ++mi) {
                const uint32_t off = (uint32_t)(wm + mi * 16 + (lane & 15)) * ROWB + colb;
                const uint32_t addr = sa + (off ^ ((off >> 3) & 0x70u));
                asm volatile("ldmatrix.sync.aligned.m8n8.x4.shared.b16 {%0,%1,%2,%3}, [%4];"
                             : "=r"(af[mi][0]), "=r"(af[mi][1]), "=r"(af[mi][2]), "=r"(af[mi][3])
                             : "r"(addr));
            }
#pragma unroll
            for (int np = 0; np < 2; ++np) {
                const uint32_t off = (uint32_t)(wn + np * 16 + (lane & 15)) * ROWB + colb;
                const uint32_t addr = sb + (off ^ ((off >> 3) & 0x70u));
                asm volatile("ldmatrix.sync.aligned.m8n8.x4.shared.b16 {%0,%1,%2,%3}, [%4];"
                             : "=r"(bf[np][0]), "=r"(bf[np][1]), "=r"(bf[np][2]), "=r"(bf[np][3])
                             : "r"(addr));
            }
#pragma unroll
            for (int mi = 0; mi < 4; ++mi) {
#pragma unroll
                for (int np = 0; np < 2; ++np) {
                    asm volatile(
                        "mma.sync.aligned.m16n8k16.row.col.f32.f16.f16.f32 "
                        "{%0,%1,%2,%3}, {%4,%5,%6,%7}, {%8,%9}, {%0,%1,%2,%3};"
                        : "+f"(acc[mi][np*2][0]), "+f"(acc[mi][np*2][1]),
                          "+f"(acc[mi][np*2][2]), "+f"(acc[mi][np*2][3])
                        : "r"(af[mi][0]), "r"(af[mi][1]), "r"(af[mi][2]), "r"(af[mi][3]),
                          "r"(bf[np][0]), "r"(bf[np][2]));
                    asm volatile(
                        "mma.sync.aligned.m16n8k16.row.col.f32.f16.f16.f32 "
                        "{%0,%1,%2,%3}, {%4,%5,%6,%7}, {%8,%9}, {%0,%1,%2,%3};"
                        : "+f"(acc[mi][np*2+1][0]), "+f"(acc[mi][np*2+1][1]),
                          "+f"(acc[mi][np*2+1][2]), "+f"(acc[mi][np*2+1][3])
                        : "r"(af[mi][0]), "r"(af[mi][1]), "r"(af[mi][2]), "r"(af[mi][3]),
                          "r"(bf[np][1]), "r"(bf[np][3]));
                }
            }
        }
    }

    // epilogue
    const int r0 = mBase + wm + (lane >> 2);
    const int c0 = nBase + wn + (lane & 3) * 2;
#pragma unroll
    for (int mi = 0; mi < 4; ++mi) {
#pragma unroll
        for (int ni = 0; ni < 4; ++ni) {
            const int r = r0 + mi * 16;
            const int c = c0 + ni * 8;
            *(float2*)(out + (size_t)r * HIDDEN + c)       = make_float2(acc[mi][ni][0], acc[mi][ni][1]);
            *(float2*)(out + (size_t)(r + 8) * HIDDEN + c) = make_float2(acc[mi][ni][2], acc[mi][ni][3]);
        }
    }
}

// ---------------------------------------------------------------------------
// Kernel 2: in-place RMS-norm, 4 rows per 512-thread block (128 threads/row)
//   x * sqrt(H) / sqrt(sum x^2 + EPS*H) * w
// ---------------------------------------------------------------------------
__global__ void __launch_bounds__(512)
rmsnorm_kernel(float* __restrict__ out, const float* __restrict__ nw) {
    const int rg  = threadIdx.x >> 7;        // row group within block: 0..3
    const int t   = threadIdx.x & 127;       // thread within row: 0..127
    const int row = blockIdx.x * 4 + rg;

    float4* p = (float4*)(out + (size_t)row * HIDDEN);
    float4 v0 = p[t];
    float4 v1 = p[t + 128];

    float ss = v0.x*v0.x + v0.y*v0.y + v0.z*v0.z + v0.w*v0.w
             + v1.x*v1.x + v1.y*v1.y + v1.z*v1.z + v1.w*v1.w;
#pragma unroll
    for (int o = 16; o > 0; o >>= 1) ss += __shfl_xor_sync(0xFFFFFFFFu, ss, o);

    __shared__ float sred[16];                // 4 rows x 4 warps
    if ((t & 31) == 0) sred[rg * 4 + (t >> 5)] = ss;
    __syncthreads();
    const float tot = sred[rg*4+0] + sred[rg*4+1] + sred[rg*4+2] + sred[rg*4+3];
    const float sc  = 32.0f * rsqrtf(tot + 1.024e-3f);   // sqrt(H)/sqrt(ss+EPS*H)

    const float4 w0 = ((const float4*)nw)[t];
    const float4 w1 = ((const float4*)nw)[t + 128];
    v0.x *= sc * w0.x; v0.y *= sc * w0.y; v0.z *= sc * w0.z; v0.w *= sc * w0.w;
    v1.x *= sc * w1.x; v1.y *= sc * w1.y; v1.z *= sc * w1.z; v1.w *= sc * w1.w;
    p[t]       = v0;
    p[t + 128] = v1;
}

// ---------------------------------------------------------------------------
extern "C" void kernel_launch(void* const* d_in, const int* in_sizes, int n_in,
                              void* d_out, int out_size) {
    const float* x  = (const float*)d_in[0];   // [2,4096,1024] fp32
    const float* cw = (const float*)d_in[1];   // [20,1024,1024] fp32
    const float* nw = (const float*)d_in[2];   // [1024] fp32
    float* out = (float*)d_out;                // [2,4096,1024] fp32
    (void)in_sizes; (void)n_in; (void)out_size;

    prep_kernel<<<WSUM_BLOCKS + X_BLOCKS, 256>>>(x, cw);   // 2048 blocks

    cudaFuncSetAttribute(gemm_kernel, cudaFuncAttributeMaxDynamicSharedMemorySize, SMEM_BYTES);
    dim3 grid(HIDDEN / BN, M_TOTAL / BM);   // (8, 64) = 512 CTAs
    gemm_kernel<<<grid, 256, SMEM_BYTES>>>(out);

    rmsnorm_kernel<<<M_TOTAL / 4, 512>>>(out, nw);
}